// round 14
// baseline (speedup 1.0000x reference)
#include <cuda_runtime.h>
#include <cuda_fp16.h>
#include <math.h>

#define EMB    1024
#define HEADS  16
#define DHEAD  64
#define WINDOW 128
#define BATCH  2
#define SEQ    2048
#define MTOT   (BATCH * SEQ)

// log2(e)/32 : folded into Q so softmax uses exp2
#define QSCALE 0.04508422f

// ---------------------------------------------------------------------------
// Device-global scratch
// ---------------------------------------------------------------------------
__device__ __half g_xhi[MTOT * EMB];
__device__ __half g_qhi[MTOT * EMB];
__device__ __half g_khi[MTOT * EMB];
__device__ __half g_vhi[MTOT * EMB];
__device__ __half g_ahi[MTOT * EMB];
__device__ __half g_whi[4 * EMB * EMB];   // transposed: [n][k], fp16

// ---------------------------------------------------------------------------
// PTX helpers
// ---------------------------------------------------------------------------
__device__ __forceinline__ unsigned s2u(const void* p) {
    unsigned a;
    asm("{ .reg .u64 t; cvta.to.shared.u64 t, %1; cvt.u32.u64 %0, t; }"
        : "=r"(a) : "l"(p));
    return a;
}
__device__ __forceinline__ void cp16(unsigned s, const void* g) {
    asm volatile("cp.async.cg.shared.global [%0], [%1], 16;" :: "r"(s), "l"(g));
}
#define CPA_COMMIT() asm volatile("cp.async.commit_group;" ::: "memory")
#define CPA_WAIT1()  asm volatile("cp.async.wait_group 1;" ::: "memory")
#define CPA_WAIT2()  asm volatile("cp.async.wait_group 2;" ::: "memory")

__device__ __forceinline__ void ldsm4(unsigned* r, unsigned a) {
    asm volatile("ldmatrix.sync.aligned.m8n8.x4.shared.b16 {%0,%1,%2,%3}, [%4];"
                 : "=r"(r[0]), "=r"(r[1]), "=r"(r[2]), "=r"(r[3]) : "r"(a));
}
__device__ __forceinline__ void ldsm4t(unsigned* r, unsigned a) {
    asm volatile("ldmatrix.sync.aligned.m8n8.x4.trans.shared.b16 {%0,%1,%2,%3}, [%4];"
                 : "=r"(r[0]), "=r"(r[1]), "=r"(r[2]), "=r"(r[3]) : "r"(a));
}
__device__ __forceinline__ void mma16816(float* c, const unsigned* a, const unsigned* b) {
    asm volatile(
        "mma.sync.aligned.m16n8k16.row.col.f32.f16.f16.f32 "
        "{%0,%1,%2,%3}, {%4,%5,%6,%7}, {%8,%9}, {%0,%1,%2,%3};"
        : "+f"(c[0]), "+f"(c[1]), "+f"(c[2]), "+f"(c[3])
        : "r"(a[0]), "r"(a[1]), "r"(a[2]), "r"(a[3]), "r"(b[0]), "r"(b[1]));
}

// guaranteed-MUFU exp2
__device__ __forceinline__ float ex2(float x) {
    float y;
    asm("ex2.approx.ftz.f32 %0, %1;" : "=f"(y) : "f"(x));
    return y;
}

// swizzled smem byte offset for (row, 16B-segment): rows of 128 bytes
__device__ __forceinline__ unsigned swz(int row, int seg) {
    return (unsigned)(row * 128 + ((seg ^ (row & 7)) << 4));
}

__device__ __forceinline__ unsigned pack2h(float a, float b) {
    __half2 h = __floats2half2_rn(a, b);
    return *reinterpret_cast<unsigned*>(&h);
}

// ---------------------------------------------------------------------------
// Merged conversion kernel: z=0..3 -> transpose+convert W_z; z=4..7 -> x->fp16
// grid (32, 32, 8), block (32, 8) = 256 threads
// ---------------------------------------------------------------------------
__global__ void convert_kernel(
    const float* __restrict__ x,
    const float* __restrict__ w0, const float* __restrict__ w1,
    const float* __restrict__ w2, const float* __restrict__ w3,
    __half* __restrict__ xhi, __half* __restrict__ whi)
{
    int z = blockIdx.z;
    if (z < 4) {
        __shared__ float t[32][33];
        const float* W = (z == 0) ? w0 : (z == 1) ? w1 : (z == 2) ? w2 : w3;
        int n0 = blockIdx.x * 32, k0 = blockIdx.y * 32;
        #pragma unroll
        for (int i = 0; i < 4; i++) {
            int k = threadIdx.y + i * 8;
            t[k][threadIdx.x] = W[(size_t)(k0 + k) * EMB + n0 + threadIdx.x];
        }
        __syncthreads();
        size_t base = (size_t)z * EMB * EMB;
        #pragma unroll
        for (int i = 0; i < 4; i++) {
            int n = threadIdx.y + i * 8;
            whi[base + (size_t)(n0 + n) * EMB + k0 + threadIdx.x] =
                __float2half_rn(t[threadIdx.x][n]);
        }
    } else {
        int bid = ((z - 4) * 1024) + blockIdx.y * 32 + blockIdx.x;
        int tid = threadIdx.y * 32 + threadIdx.x;
        int i = bid * 256 + tid;
        float4 v = reinterpret_cast<const float4*>(x)[i];
        reinterpret_cast<unsigned*>(xhi)[2 * i + 0] = pack2h(v.x, v.y);
        reinterpret_cast<unsigned*>(xhi)[2 * i + 1] = pack2h(v.z, v.w);
    }
}

// ---------------------------------------------------------------------------
// 1-pass fp16 mma.sync GEMM: C = Ah @ Wh + bias
// 128x128 CTA tile, BK=64, 3-stage cp.async pipeline, 2 CTAs/SM.
// HALFOUT=true: fp16 out with per-z scale.  false: fp32 out.
// ---------------------------------------------------------------------------
#define BKC        64
#define TILE_HB    16384              // 128 rows x 128 B
#define STAGE_HB   (2 * TILE_HB)      // Ah, Bh
#define GSTAGES    3
#define NCHUNK     (EMB / BKC)        // 16
#define GEMM_SMEM  (GSTAGES * STAGE_HB)   // 98304

__device__ __forceinline__ void load_stage(
    unsigned st, int tid, int m0, int n0, int k0,
    const __half* Ah, const __half* Bh)
{
    #pragma unroll
    for (int i = 0; i < 4; i++) {
        int idx = tid + i * 256;
        int r   = idx >> 3;
        int s   = idx & 7;
        unsigned sw = swz(r, s);
        cp16(st + sw,           Ah + (size_t)(m0 + r) * EMB + k0 + s * 8);
        cp16(st + TILE_HB + sw, Bh + (size_t)(n0 + r) * EMB + k0 + s * 8);
    }
}

template<bool HALFOUT>
__global__ __launch_bounds__(256, 2) void gemm_mma(
    const __half* __restrict__ Ahi,
    const __half* __restrict__ Whi,
    const float* __restrict__ b0, const float* __restrict__ b1, const float* __restrict__ b2,
    float* __restrict__ Cf0,
    __half* __restrict__ Ch0, __half* __restrict__ Ch1, __half* __restrict__ Ch2,
    float s0, float s1, float s2)
{
    extern __shared__ char smc[];
    const int z = blockIdx.z;
    const float* bias = (z == 0) ? b0 : (z == 1) ? b1 : b2;
    __half* Ch = (z == 0) ? Ch0 : (z == 1) ? Ch1 : Ch2;
    float scale = (z == 0) ? s0 : (z == 1) ? s1 : s2;
    const __half* Bh = Whi + (size_t)z * EMB * EMB;
    const int m0  = blockIdx.y * 128;
    const int n0  = blockIdx.x * 128;
    const int tid = threadIdx.x;
    const int wid = tid >> 5, lane = tid & 31;
    const int wm  = wid & 1;
    const int wn  = wid >> 1;
    const unsigned sb = s2u(smc);

    float acc[4][4][4];
    #pragma unroll
    for (int mt = 0; mt < 4; mt++)
        #pragma unroll
        for (int nt = 0; nt < 4; nt++)
            #pragma unroll
            for (int e = 0; e < 4; e++) acc[mt][nt][e] = 0.0f;

    load_stage(sb,                tid, m0, n0, 0,       Ahi, Bh);
    CPA_COMMIT();
    load_stage(sb + STAGE_HB,     tid, m0, n0, BKC,     Ahi, Bh);
    CPA_COMMIT();
    load_stage(sb + 2 * STAGE_HB, tid, m0, n0, 2 * BKC, Ahi, Bh);
    CPA_COMMIT();

    const int arow  = wm * 64 + (lane & 15);                      // + mt*16
    const int aseg  = lane >> 4;
    const int brow4 = wn * 32 + ((lane >> 4) << 3) + (lane & 7);  // + nth*16
    const int bseg  = (lane >> 3) & 1;

    for (int c = 0; c < NCHUNK; c++) {
        unsigned st = sb + (unsigned)(c % GSTAGES) * STAGE_HB;
        CPA_WAIT2();
        __syncthreads();

        #pragma unroll
        for (int k8 = 0; k8 < 8; k8 += 2) {
            unsigned bh[4][2];
            #pragma unroll
            for (int nth = 0; nth < 2; nth++) {
                unsigned off = swz(brow4 + nth * 16, k8 + bseg);
                unsigned t4[4];
                ldsm4(t4, st + TILE_HB + off);
                bh[2 * nth][0] = t4[0]; bh[2 * nth][1] = t4[1];
                bh[2 * nth + 1][0] = t4[2]; bh[2 * nth + 1][1] = t4[3];
            }
            #pragma unroll
            for (int mt = 0; mt < 4; mt++) {
                unsigned off = swz(arow + mt * 16, k8 + aseg);
                unsigned ah[4];
                ldsm4(ah, st + off);
                #pragma unroll
                for (int nt = 0; nt < 4; nt++)
                    mma16816(acc[mt][nt], ah, bh[nt]);
            }
        }
        __syncthreads();
        int cn = c + 3;
        if (cn < NCHUNK) {
            load_stage(st, tid, m0, n0, cn * BKC, Ahi, Bh);
            CPA_COMMIT();
        }
    }

    #pragma unroll
    for (int mt = 0; mt < 4; mt++) {
        int rbase = m0 + wm * 64 + mt * 16 + (lane >> 2);
        #pragma unroll
        for (int nt = 0; nt < 4; nt++) {
            int col = n0 + wn * 32 + nt * 8 + 2 * (lane & 3);
            float2 bv = *reinterpret_cast<const float2*>(&bias[col]);
            float v0 = acc[mt][nt][0] + bv.x;
            float v1 = acc[mt][nt][1] + bv.y;
            float v2 = acc[mt][nt][2] + bv.x;
            float v3 = acc[mt][nt][3] + bv.y;
            if (HALFOUT) {
                *reinterpret_cast<unsigned*>(&Ch[(size_t)rbase * EMB + col]) =
                    pack2h(v0 * scale, v1 * scale);
                *reinterpret_cast<unsigned*>(&Ch[(size_t)(rbase + 8) * EMB + col]) =
                    pack2h(v2 * scale, v3 * scale);
            } else {
                float2 o0 = {v0, v1}, o1 = {v2, v3};
                *reinterpret_cast<float2*>(&Cf0[(size_t)rbase * EMB + col]) = o0;
                *reinterpret_cast<float2*>(&Cf0[(size_t)(rbase + 8) * EMB + col]) = o1;
            }
        }
    }
}

// ---------------------------------------------------------------------------
// Tensor-core windowed attention, fp16 K/V, MUFU softmax.
// Q tile 64, 128 threads, 3-stage cp.async pipeline, one sync per tile.
// Q fragments re-loaded from smem per tile to cut regs; target 5 CTAs/SM.
// ---------------------------------------------------------------------------
#define KV_TILE   8192                 // 64 rows x 128 B
#define KV_STAGE  (2 * KV_TILE)        // Kh, Vh
#define ASTAGES   3
#define ATTN_SMEM (KV_TILE + ASTAGES * KV_STAGE)   // 57344

__device__ __forceinline__ void load_kv(
    unsigned st, int tid, int b, int kt, int h,
    const __half* Kh, const __half* Vh)
{
    #pragma unroll
    for (int i = 0; i < 4; i++) {
        int idx = tid + i * 128;
        int r = idx >> 3, s = idx & 7;
        unsigned sw = swz(r, s);
        size_t g = (size_t)(b * SEQ + kt + r) * EMB + h * DHEAD + s * 8;
        cp16(st + sw,           Kh + g);
        cp16(st + KV_TILE + sw, Vh + g);
    }
}

__global__ __launch_bounds__(128, 5) void attn_mma(
    const __half* __restrict__ Qh,
    const __half* __restrict__ Kh,
    const __half* __restrict__ Vh,
    __half* __restrict__ Ohi)
{
    extern __shared__ char smb[];
    const unsigned sb = s2u(smb);
    const unsigned Qhi_s = sb;
    const unsigned st0   = sb + KV_TILE;

    const int tid = threadIdx.x, wid = tid >> 5, lane = tid & 31;
    const int q0 = blockIdx.x * 64, h = blockIdx.y, b = blockIdx.z;

    int kstart = q0 - 128; if (kstart < 0) kstart = 0;
    int kend   = q0 + 192; if (kend > SEQ) kend = SEQ;
    const int ntiles = (kend - kstart) >> 6;   // 3..5

    {
        const size_t qg = (size_t)(b * SEQ + q0) * EMB + h * DHEAD;
        #pragma unroll
        for (int i = 0; i < 4; i++) {
            int idx = tid + i * 128;
            int r = idx >> 3, s = idx & 7;
            cp16(Qhi_s + swz(r, s), Qh + qg + (size_t)r * EMB + s * 8);
        }
    }
    CPA_COMMIT();
    load_kv(st0,            tid, b, kstart,      h, Kh, Vh);
    CPA_COMMIT();
    load_kv(st0 + KV_STAGE, tid, b, kstart + 64, h, Kh, Vh);
    CPA_COMMIT();

    CPA_WAIT2();
    __syncthreads();

    const int qrow = wid * 16 + (lane & 15);
    const int qks  = lane >> 4;

    float o[8][4];
    #pragma unroll
    for (int i = 0; i < 8; i++)
        #pragma unroll
        for (int e = 0; e < 4; e++) o[i][e] = 0.0f;
    float m0 = -1e30f, m1 = -1e30f, l0 = 0.0f, l1 = 0.0f;

    for (int t = 0; t < ntiles; t++) {
        CPA_WAIT1();
        __syncthreads();

        int tn = t + 2;
        if (tn < ntiles) {
            load_kv(st0 + (unsigned)(tn % ASTAGES) * KV_STAGE,
                    tid, b, kstart + tn * 64, h, Kh, Vh);
            CPA_COMMIT();
        }

        unsigned st = st0 + (unsigned)(t % ASTAGES) * KV_STAGE;
        const int kt = kstart + t * 64;

        // ---- S = Q K^T  (Q fragments re-loaded from resident smem) ----
        float s[8][4];
        #pragma unroll
        for (int i = 0; i < 8; i++)
            #pragma unroll
            for (int e = 0; e < 4; e++) s[i][e] = 0.0f;

        #pragma unroll
        for (int kc = 0; kc < 4; kc++) {
            unsigned qf[4];
            ldsm4(qf, Qhi_s + swz(qrow, kc * 2 + qks));
            #pragma unroll
            for (int np = 0; np < 4; np++) {
                int krow = np * 16 + ((lane >> 4) << 3) + (lane & 7);
                unsigned off = swz(krow, kc * 2 + ((lane >> 3) & 1));
                unsigned kb[4];
                ldsm4(kb, st + off);
                mma16816(s[2 * np],     qf, kb);
                mma16816(s[2 * np + 1], qf, kb + 2);
            }
        }

        // ---- window mask (only edge tiles) ----
        if (kt == q0 + 128 || kt + 128 == q0) {
            int iqb = q0 + wid * 16 + (lane >> 2);
            int jkb = kt + 2 * (lane & 3);
            #pragma unroll
            for (int nt = 0; nt < 8; nt++)
                #pragma unroll
                for (int e = 0; e < 4; e++) {
                    int iq = iqb + ((e >> 1) << 3);
                    int jk = jkb + nt * 8 + (e & 1);
                    int d = iq - jk; if (d < 0) d = -d;
                    if (d > WINDOW) s[nt][e] = -1e30f;
                }
        }

        // ---- online softmax (MUFU exp2) ----
        float mx0 = -1e30f, mx1 = -1e30f;
        #pragma unroll
        for (int nt = 0; nt < 8; nt++) {
            mx0 = fmaxf(mx0, fmaxf(s[nt][0], s[nt][1]));
            mx1 = fmaxf(mx1, fmaxf(s[nt][2], s[nt][3]));
        }
        mx0 = fmaxf(mx0, __shfl_xor_sync(0xffffffffu, mx0, 1));
        mx0 = fmaxf(mx0, __shfl_xor_sync(0xffffffffu, mx0, 2));
        mx1 = fmaxf(mx1, __shfl_xor_sync(0xffffffffu, mx1, 1));
        mx1 = fmaxf(mx1, __shfl_xor_sync(0xffffffffu, mx1, 2));
        float nm0 = fmaxf(m0, mx0), nm1 = fmaxf(m1, mx1);
        float c0 = ex2(m0 - nm0), c1 = ex2(m1 - nm1);
        m0 = nm0; m1 = nm1;
        l0 *= c0;  l1 *= c1;
        #pragma unroll
        for (int nt = 0; nt < 8; nt++) {
            o[nt][0] *= c0; o[nt][1] *= c0;
            o[nt][2] *= c1; o[nt][3] *= c1;
        }

        unsigned pha[4][4];
        #pragma unroll
        for (int np = 0; np < 4; np++) {
            float pe0 = ex2(s[2 * np][0] - m0), pe1 = ex2(s[2 * np][1] - m0);
            float pe2 = ex2(s[2 * np][2] - m1), pe3 = ex2(s[2 * np][3] - m1);
            float po0 = ex2(s[2 * np + 1][0] - m0), po1 = ex2(s[2 * np + 1][1] - m0);
            float po2 = ex2(s[2 * np + 1][2] - m1), po3 = ex2(s[2 * np + 1][3] - m1);
            l0 += pe0 + pe1 + po0 + po1;
            l1 += pe2 + pe3 + po2 + po3;
            pha[np][0] = pack2h(pe0, pe1);
            pha[np][1] = pack2h(pe2, pe3);
            pha[np][2] = pack2h(po0, po1);
            pha[np][3] = pack2h(po2, po3);
        }

        // ---- O += P V ----
        #pragma unroll
        for (int kc2 = 0; kc2 < 4; kc2++) {
            int vrow = kc2 * 16 + (lane & 15);
            #pragma unroll
            for (int dp = 0; dp < 4; dp++) {
                unsigned off = swz(vrow, dp * 2 + (lane >> 4));
                unsigned vb[4];
                ldsm4t(vb, st + KV_TILE + off);
                mma16816(o[2 * dp],     pha[kc2], vb);
                mma16816(o[2 * dp + 1], pha[kc2], vb + 2);
            }
        }
    }

    l0 += __shfl_xor_sync(0xffffffffu, l0, 1);
    l0 += __shfl_xor_sync(0xffffffffu, l0, 2);
    l1 += __shfl_xor_sync(0xffffffffu, l1, 1);
    l1 += __shfl_xor_sync(0xffffffffu, l1, 2);
    float inv0 = 1.0f / l0, inv1 = 1.0f / l1;

    int row0 = q0 + wid * 16 + (lane >> 2);
    size_t t0 = (size_t)(b * SEQ + row0) * EMB + h * DHEAD;
    size_t t1 = t0 + (size_t)8 * EMB;
    #pragma unroll
    for (int nt = 0; nt < 8; nt++) {
        int col = nt * 8 + 2 * (lane & 3);
        *reinterpret_cast<unsigned*>(&Ohi[t0 + col]) = pack2h(o[nt][0] * inv0, o[nt][1] * inv0);
        *reinterpret_cast<unsigned*>(&Ohi[t1 + col]) = pack2h(o[nt][2] * inv1, o[nt][3] * inv1);
    }
}

// ---------------------------------------------------------------------------
// Launch
// ---------------------------------------------------------------------------
extern "C" void kernel_launch(void* const* d_in, const int* in_sizes, int n_in,
                              void* d_out, int out_size)
{
    const float* x  = (const float*)d_in[0];
    const float* wq = (const float*)d_in[1];
    const float* bq = (const float*)d_in[2];
    const float* wk = (const float*)d_in[3];
    const float* bk = (const float*)d_in[4];
    const float* wv = (const float*)d_in[5];
    const float* bv = (const float*)d_in[6];
    const float* wo = (const float*)d_in[7];
    const float* bo = (const float*)d_in[8];
    float* out = (float*)d_out;

    __half *xhi, *qhi, *khi, *vhi, *ahi, *whi;
    cudaGetSymbolAddress((void**)&xhi, g_xhi);
    cudaGetSymbolAddress((void**)&qhi, g_qhi);
    cudaGetSymbolAddress((void**)&khi, g_khi);
    cudaGetSymbolAddress((void**)&vhi, g_vhi);
    cudaGetSymbolAddress((void**)&ahi, g_ahi);
    cudaGetSymbolAddress((void**)&whi, g_whi);

    cudaFuncSetAttribute(gemm_mma<true>,  cudaFuncAttributeMaxDynamicSharedMemorySize, GEMM_SMEM);
    cudaFuncSetAttribute(gemm_mma<false>, cudaFuncAttributeMaxDynamicSharedMemorySize, GEMM_SMEM);
    cudaFuncSetAttribute(attn_mma, cudaFuncAttributeMaxDynamicSharedMemorySize, ATTN_SMEM);

    // 1) merged conversions: W transpose (z=0..3) + x fp16 convert (z=4..7)
    convert_kernel<<<dim3(32, 32, 8), dim3(32, 8)>>>(x, wq, wk, wv, wo, xhi, whi);

    // 2) QKV projections -> fp16 (Q pre-scaled by log2e/32)
    gemm_mma<true><<<dim3(8, 32, 3), 256, GEMM_SMEM>>>(
        xhi, whi, bq, bk, bv,
        nullptr,
        qhi, khi, vhi,
        QSCALE, 1.0f, 1.0f);

    // 3) Tensor-core windowed attention -> fp16
    attn_mma<<<dim3(SEQ / 64, HEADS, BATCH), 128, ATTN_SMEM>>>(
        qhi, khi, vhi, ahi);

    // 4) Output projection -> fp32
    gemm_mma<false><<<dim3(8, 32, 1), 256, GEMM_SMEM>>>(
        ahi, whi + (size_t)3 * EMB * EMB,
        bo, bo, bo,
        out,
        nullptr, nullptr, nullptr,
        1.0f, 1.0f, 1.0f);
}

// round 15
// speedup vs baseline: 1.0141x; 1.0141x over previous
#include <cuda_runtime.h>
#include <cuda_fp16.h>
#include <math.h>

#define EMB    1024
#define HEADS  16
#define DHEAD  64
#define WINDOW 128
#define BATCH  2
#define SEQ    2048
#define MTOT   (BATCH * SEQ)

// log2(e)/32 : folded into Q so softmax uses exp2
#define QSCALE 0.04508422f

// ---------------------------------------------------------------------------
// Device-global scratch
// ---------------------------------------------------------------------------
__device__ __half g_xhi[MTOT * EMB];
__device__ __half g_qhi[MTOT * EMB];
__device__ __half g_khi[MTOT * EMB];
__device__ __half g_vhi[MTOT * EMB];
__device__ __half g_ahi[MTOT * EMB];
__device__ __half g_whi[4 * EMB * EMB];   // transposed: [n][k], fp16

// ---------------------------------------------------------------------------
// PTX helpers
// ---------------------------------------------------------------------------
__device__ __forceinline__ unsigned s2u(const void* p) {
    unsigned a;
    asm("{ .reg .u64 t; cvta.to.shared.u64 t, %1; cvt.u32.u64 %0, t; }"
        : "=r"(a) : "l"(p));
    return a;
}
__device__ __forceinline__ void cp16(unsigned s, const void* g) {
    asm volatile("cp.async.cg.shared.global [%0], [%1], 16;" :: "r"(s), "l"(g));
}
#define CPA_COMMIT() asm volatile("cp.async.commit_group;" ::: "memory")
#define CPA_WAIT1()  asm volatile("cp.async.wait_group 1;" ::: "memory")
#define CPA_WAIT2()  asm volatile("cp.async.wait_group 2;" ::: "memory")

__device__ __forceinline__ void ldsm4(unsigned* r, unsigned a) {
    asm volatile("ldmatrix.sync.aligned.m8n8.x4.shared.b16 {%0,%1,%2,%3}, [%4];"
                 : "=r"(r[0]), "=r"(r[1]), "=r"(r[2]), "=r"(r[3]) : "r"(a));
}
__device__ __forceinline__ void ldsm4t(unsigned* r, unsigned a) {
    asm volatile("ldmatrix.sync.aligned.m8n8.x4.trans.shared.b16 {%0,%1,%2,%3}, [%4];"
                 : "=r"(r[0]), "=r"(r[1]), "=r"(r[2]), "=r"(r[3]) : "r"(a));
}
__device__ __forceinline__ void mma16816(float* c, const unsigned* a, const unsigned* b) {
    asm volatile(
        "mma.sync.aligned.m16n8k16.row.col.f32.f16.f16.f32 "
        "{%0,%1,%2,%3}, {%4,%5,%6,%7}, {%8,%9}, {%0,%1,%2,%3};"
        : "+f"(c[0]), "+f"(c[1]), "+f"(c[2]), "+f"(c[3])
        : "r"(a[0]), "r"(a[1]), "r"(a[2]), "r"(a[3]), "r"(b[0]), "r"(b[1]));
}

// guaranteed-MUFU exp2
__device__ __forceinline__ float ex2(float x) {
    float y;
    asm("ex2.approx.ftz.f32 %0, %1;" : "=f"(y) : "f"(x));
    return y;
}

// swizzled smem byte offset for (row, 16B-segment): rows of 128 bytes
__device__ __forceinline__ unsigned swz(int row, int seg) {
    return (unsigned)(row * 128 + ((seg ^ (row & 7)) << 4));
}

__device__ __forceinline__ unsigned pack2h(float a, float b) {
    __half2 h = __floats2half2_rn(a, b);
    return *reinterpret_cast<unsigned*>(&h);
}

// ---------------------------------------------------------------------------
// Merged conversion kernel: z=0..3 -> transpose+convert W_z; z=4..7 -> x->fp16
// grid (32, 32, 8), block (32, 8) = 256 threads
// ---------------------------------------------------------------------------
__global__ void convert_kernel(
    const float* __restrict__ x,
    const float* __restrict__ w0, const float* __restrict__ w1,
    const float* __restrict__ w2, const float* __restrict__ w3,
    __half* __restrict__ xhi, __half* __restrict__ whi)
{
    int z = blockIdx.z;
    if (z < 4) {
        __shared__ float t[32][33];
        const float* W = (z == 0) ? w0 : (z == 1) ? w1 : (z == 2) ? w2 : w3;
        int n0 = blockIdx.x * 32, k0 = blockIdx.y * 32;
        #pragma unroll
        for (int i = 0; i < 4; i++) {
            int k = threadIdx.y + i * 8;
            t[k][threadIdx.x] = W[(size_t)(k0 + k) * EMB + n0 + threadIdx.x];
        }
        __syncthreads();
        size_t base = (size_t)z * EMB * EMB;
        #pragma unroll
        for (int i = 0; i < 4; i++) {
            int n = threadIdx.y + i * 8;
            whi[base + (size_t)(n0 + n) * EMB + k0 + threadIdx.x] =
                __float2half_rn(t[threadIdx.x][n]);
        }
    } else {
        int bid = ((z - 4) * 1024) + blockIdx.y * 32 + blockIdx.x;
        int tid = threadIdx.y * 32 + threadIdx.x;
        int i = bid * 256 + tid;
        float4 v = reinterpret_cast<const float4*>(x)[i];
        reinterpret_cast<unsigned*>(xhi)[2 * i + 0] = pack2h(v.x, v.y);
        reinterpret_cast<unsigned*>(xhi)[2 * i + 1] = pack2h(v.z, v.w);
    }
}

// ---------------------------------------------------------------------------
// 1-pass fp16 mma.sync GEMM: C = Ah @ Wh + bias
// 128x128 CTA tile, BK=64, 3-stage cp.async pipeline, 2 CTAs/SM.
// HALFOUT=true: fp16 out with per-z scale.  false: fp32 out.
// ---------------------------------------------------------------------------
#define BKC        64
#define TILE_HB    16384              // 128 rows x 128 B
#define STAGE_HB   (2 * TILE_HB)      // Ah, Bh
#define GSTAGES    3
#define NCHUNK     (EMB / BKC)        // 16
#define GEMM_SMEM  (GSTAGES * STAGE_HB)   // 98304

__device__ __forceinline__ void load_stage(
    unsigned st, int tid, int m0, int n0, int k0,
    const __half* Ah, const __half* Bh)
{
    #pragma unroll
    for (int i = 0; i < 4; i++) {
        int idx = tid + i * 256;
        int r   = idx >> 3;
        int s   = idx & 7;
        unsigned sw = swz(r, s);
        cp16(st + sw,           Ah + (size_t)(m0 + r) * EMB + k0 + s * 8);
        cp16(st + TILE_HB + sw, Bh + (size_t)(n0 + r) * EMB + k0 + s * 8);
    }
}

template<bool HALFOUT>
__global__ __launch_bounds__(256, 2) void gemm_mma(
    const __half* __restrict__ Ahi,
    const __half* __restrict__ Whi,
    const float* __restrict__ b0, const float* __restrict__ b1, const float* __restrict__ b2,
    float* __restrict__ Cf0,
    __half* __restrict__ Ch0, __half* __restrict__ Ch1, __half* __restrict__ Ch2,
    float s0, float s1, float s2)
{
    extern __shared__ char smc[];
    const int z = blockIdx.z;
    const float* bias = (z == 0) ? b0 : (z == 1) ? b1 : b2;
    __half* Ch = (z == 0) ? Ch0 : (z == 1) ? Ch1 : Ch2;
    float scale = (z == 0) ? s0 : (z == 1) ? s1 : s2;
    const __half* Bh = Whi + (size_t)z * EMB * EMB;
    const int m0  = blockIdx.y * 128;
    const int n0  = blockIdx.x * 128;
    const int tid = threadIdx.x;
    const int wid = tid >> 5, lane = tid & 31;
    const int wm  = wid & 1;
    const int wn  = wid >> 1;
    const unsigned sb = s2u(smc);

    float acc[4][4][4];
    #pragma unroll
    for (int mt = 0; mt < 4; mt++)
        #pragma unroll
        for (int nt = 0; nt < 4; nt++)
            #pragma unroll
            for (int e = 0; e < 4; e++) acc[mt][nt][e] = 0.0f;

    load_stage(sb,                tid, m0, n0, 0,       Ahi, Bh);
    CPA_COMMIT();
    load_stage(sb + STAGE_HB,     tid, m0, n0, BKC,     Ahi, Bh);
    CPA_COMMIT();
    load_stage(sb + 2 * STAGE_HB, tid, m0, n0, 2 * BKC, Ahi, Bh);
    CPA_COMMIT();

    const int arow  = wm * 64 + (lane & 15);                      // + mt*16
    const int aseg  = lane >> 4;
    const int brow4 = wn * 32 + ((lane >> 4) << 3) + (lane & 7);  // + nth*16
    const int bseg  = (lane >> 3) & 1;

    for (int c = 0; c < NCHUNK; c++) {
        unsigned st = sb + (unsigned)(c % GSTAGES) * STAGE_HB;
        CPA_WAIT2();
        __syncthreads();

        #pragma unroll
        for (int k8 = 0; k8 < 8; k8 += 2) {
            unsigned bh[4][2];
            #pragma unroll
            for (int nth = 0; nth < 2; nth++) {
                unsigned off = swz(brow4 + nth * 16, k8 + bseg);
                unsigned t4[4];
                ldsm4(t4, st + TILE_HB + off);
                bh[2 * nth][0] = t4[0]; bh[2 * nth][1] = t4[1];
                bh[2 * nth + 1][0] = t4[2]; bh[2 * nth + 1][1] = t4[3];
            }
            #pragma unroll
            for (int mt = 0; mt < 4; mt++) {
                unsigned off = swz(arow + mt * 16, k8 + aseg);
                unsigned ah[4];
                ldsm4(ah, st + off);
                #pragma unroll
                for (int nt = 0; nt < 4; nt++)
                    mma16816(acc[mt][nt], ah, bh[nt]);
            }
        }
        __syncthreads();
        int cn = c + 3;
        if (cn < NCHUNK) {
            load_stage(st, tid, m0, n0, cn * BKC, Ahi, Bh);
            CPA_COMMIT();
        }
    }

    #pragma unroll
    for (int mt = 0; mt < 4; mt++) {
        int rbase = m0 + wm * 64 + mt * 16 + (lane >> 2);
        #pragma unroll
        for (int nt = 0; nt < 4; nt++) {
            int col = n0 + wn * 32 + nt * 8 + 2 * (lane & 3);
            float2 bv = *reinterpret_cast<const float2*>(&bias[col]);
            float v0 = acc[mt][nt][0] + bv.x;
            float v1 = acc[mt][nt][1] + bv.y;
            float v2 = acc[mt][nt][2] + bv.x;
            float v3 = acc[mt][nt][3] + bv.y;
            if (HALFOUT) {
                *reinterpret_cast<unsigned*>(&Ch[(size_t)rbase * EMB + col]) =
                    pack2h(v0 * scale, v1 * scale);
                *reinterpret_cast<unsigned*>(&Ch[(size_t)(rbase + 8) * EMB + col]) =
                    pack2h(v2 * scale, v3 * scale);
            } else {
                float2 o0 = {v0, v1}, o1 = {v2, v3};
                *reinterpret_cast<float2*>(&Cf0[(size_t)rbase * EMB + col]) = o0;
                *reinterpret_cast<float2*>(&Cf0[(size_t)(rbase + 8) * EMB + col]) = o1;
            }
        }
    }
}

// ---------------------------------------------------------------------------
// Tensor-core windowed attention, fp16 K/V, MUFU softmax. (R13 best config)
// Q tile 64, 128 threads, 3-stage cp.async pipeline, one sync per tile.
// ---------------------------------------------------------------------------
#define KV_TILE   8192                 // 64 rows x 128 B
#define KV_STAGE  (2 * KV_TILE)        // Kh, Vh
#define ASTAGES   3
#define ATTN_SMEM (KV_TILE + ASTAGES * KV_STAGE)   // 57344

__device__ __forceinline__ void load_kv(
    unsigned st, int tid, int b, int kt, int h,
    const __half* Kh, const __half* Vh)
{
    #pragma unroll
    for (int i = 0; i < 4; i++) {
        int idx = tid + i * 128;
        int r = idx >> 3, s = idx & 7;
        unsigned sw = swz(r, s);
        size_t g = (size_t)(b * SEQ + kt + r) * EMB + h * DHEAD + s * 8;
        cp16(st + sw,           Kh + g);
        cp16(st + KV_TILE + sw, Vh + g);
    }
}

__global__ __launch_bounds__(128) void attn_mma(
    const __half* __restrict__ Qh,
    const __half* __restrict__ Kh,
    const __half* __restrict__ Vh,
    __half* __restrict__ Ohi)
{
    extern __shared__ char smb[];
    const unsigned sb = s2u(smb);
    const unsigned Qhi_s = sb;
    const unsigned st0   = sb + KV_TILE;

    const int tid = threadIdx.x, wid = tid >> 5, lane = tid & 31;
    const int q0 = blockIdx.x * 64, h = blockIdx.y, b = blockIdx.z;

    int kstart = q0 - 128; if (kstart < 0) kstart = 0;
    int kend   = q0 + 192; if (kend > SEQ) kend = SEQ;
    const int ntiles = (kend - kstart) >> 6;   // 3..5

    {
        const size_t qg = (size_t)(b * SEQ + q0) * EMB + h * DHEAD;
        #pragma unroll
        for (int i = 0; i < 4; i++) {
            int idx = tid + i * 128;
            int r = idx >> 3, s = idx & 7;
            cp16(Qhi_s + swz(r, s), Qh + qg + (size_t)r * EMB + s * 8);
        }
    }
    CPA_COMMIT();
    load_kv(st0,            tid, b, kstart,      h, Kh, Vh);
    CPA_COMMIT();
    load_kv(st0 + KV_STAGE, tid, b, kstart + 64, h, Kh, Vh);
    CPA_COMMIT();

    CPA_WAIT2();
    __syncthreads();

    unsigned qfh[4][4];
    {
        int qrow = wid * 16 + (lane & 15);
        int aks  = lane >> 4;
        #pragma unroll
        for (int kc = 0; kc < 4; kc++)
            ldsm4(qfh[kc], Qhi_s + swz(qrow, kc * 2 + aks));
    }

    float o[8][4];
    #pragma unroll
    for (int i = 0; i < 8; i++)
        #pragma unroll
        for (int e = 0; e < 4; e++) o[i][e] = 0.0f;
    float m0 = -1e30f, m1 = -1e30f, l0 = 0.0f, l1 = 0.0f;

    for (int t = 0; t < ntiles; t++) {
        CPA_WAIT1();
        __syncthreads();

        int tn = t + 2;
        if (tn < ntiles) {
            load_kv(st0 + (unsigned)(tn % ASTAGES) * KV_STAGE,
                    tid, b, kstart + tn * 64, h, Kh, Vh);
            CPA_COMMIT();
        }

        unsigned st = st0 + (unsigned)(t % ASTAGES) * KV_STAGE;
        const int kt = kstart + t * 64;

        // ---- S = Q K^T ----
        float s[8][4];
        #pragma unroll
        for (int i = 0; i < 8; i++)
            #pragma unroll
            for (int e = 0; e < 4; e++) s[i][e] = 0.0f;

        #pragma unroll
        for (int np = 0; np < 4; np++) {
            int krow = np * 16 + ((lane >> 4) << 3) + (lane & 7);
            #pragma unroll
            for (int kc = 0; kc < 4; kc++) {
                unsigned off = swz(krow, kc * 2 + ((lane >> 3) & 1));
                unsigned kb[4];
                ldsm4(kb, st + off);
                mma16816(s[2 * np],     qfh[kc], kb);
                mma16816(s[2 * np + 1], qfh[kc], kb + 2);
            }
        }

        // ---- window mask (only edge tiles) ----
        if (kt == q0 + 128 || kt + 128 == q0) {
            int iqb = q0 + wid * 16 + (lane >> 2);
            int jkb = kt + 2 * (lane & 3);
            #pragma unroll
            for (int nt = 0; nt < 8; nt++)
                #pragma unroll
                for (int e = 0; e < 4; e++) {
                    int iq = iqb + ((e >> 1) << 3);
                    int jk = jkb + nt * 8 + (e & 1);
                    int d = iq - jk; if (d < 0) d = -d;
                    if (d > WINDOW) s[nt][e] = -1e30f;
                }
        }

        // ---- online softmax (MUFU exp2) ----
        float mx0 = -1e30f, mx1 = -1e30f;
        #pragma unroll
        for (int nt = 0; nt < 8; nt++) {
            mx0 = fmaxf(mx0, fmaxf(s[nt][0], s[nt][1]));
            mx1 = fmaxf(mx1, fmaxf(s[nt][2], s[nt][3]));
        }
        mx0 = fmaxf(mx0, __shfl_xor_sync(0xffffffffu, mx0, 1));
        mx0 = fmaxf(mx0, __shfl_xor_sync(0xffffffffu, mx0, 2));
        mx1 = fmaxf(mx1, __shfl_xor_sync(0xffffffffu, mx1, 1));
        mx1 = fmaxf(mx1, __shfl_xor_sync(0xffffffffu, mx1, 2));
        float nm0 = fmaxf(m0, mx0), nm1 = fmaxf(m1, mx1);
        float c0 = ex2(m0 - nm0), c1 = ex2(m1 - nm1);
        m0 = nm0; m1 = nm1;
        l0 *= c0;  l1 *= c1;
        #pragma unroll
        for (int nt = 0; nt < 8; nt++) {
            o[nt][0] *= c0; o[nt][1] *= c0;
            o[nt][2] *= c1; o[nt][3] *= c1;
        }

        unsigned pha[4][4];
        #pragma unroll
        for (int np = 0; np < 4; np++) {
            float pe0 = ex2(s[2 * np][0] - m0), pe1 = ex2(s[2 * np][1] - m0);
            float pe2 = ex2(s[2 * np][2] - m1), pe3 = ex2(s[2 * np][3] - m1);
            float po0 = ex2(s[2 * np + 1][0] - m0), po1 = ex2(s[2 * np + 1][1] - m0);
            float po2 = ex2(s[2 * np + 1][2] - m1), po3 = ex2(s[2 * np + 1][3] - m1);
            l0 += pe0 + pe1 + po0 + po1;
            l1 += pe2 + pe3 + po2 + po3;
            pha[np][0] = pack2h(pe0, pe1);
            pha[np][1] = pack2h(pe2, pe3);
            pha[np][2] = pack2h(po0, po1);
            pha[np][3] = pack2h(po2, po3);
        }

        // ---- O += P V ----
        #pragma unroll
        for (int kc2 = 0; kc2 < 4; kc2++) {
            int vrow = kc2 * 16 + (lane & 15);
            #pragma unroll
            for (int dp = 0; dp < 4; dp++) {
                unsigned off = swz(vrow, dp * 2 + (lane >> 4));
                unsigned vb[4];
                ldsm4t(vb, st + KV_TILE + off);
                mma16816(o[2 * dp],     pha[kc2], vb);
                mma16816(o[2 * dp + 1], pha[kc2], vb + 2);
            }
        }
    }

    l0 += __shfl_xor_sync(0xffffffffu, l0, 1);
    l0 += __shfl_xor_sync(0xffffffffu, l0, 2);
    l1 += __shfl_xor_sync(0xffffffffu, l1, 1);
    l1 += __shfl_xor_sync(0xffffffffu, l1, 2);
    float inv0 = 1.0f / l0, inv1 = 1.0f / l1;

    int row0 = q0 + wid * 16 + (lane >> 2);
    size_t t0 = (size_t)(b * SEQ + row0) * EMB + h * DHEAD;
    size_t t1 = t0 + (size_t)8 * EMB;
    #pragma unroll
    for (int nt = 0; nt < 8; nt++) {
        int col = nt * 8 + 2 * (lane & 3);
        *reinterpret_cast<unsigned*>(&Ohi[t0 + col]) = pack2h(o[nt][0] * inv0, o[nt][1] * inv0);
        *reinterpret_cast<unsigned*>(&Ohi[t1 + col]) = pack2h(o[nt][2] * inv1, o[nt][3] * inv1);
    }
}

// ---------------------------------------------------------------------------
// Launch
// ---------------------------------------------------------------------------
extern "C" void kernel_launch(void* const* d_in, const int* in_sizes, int n_in,
                              void* d_out, int out_size)
{
    const float* x  = (const float*)d_in[0];
    const float* wq = (const float*)d_in[1];
    const float* bq = (const float*)d_in[2];
    const float* wk = (const float*)d_in[3];
    const float* bk = (const float*)d_in[4];
    const float* wv = (const float*)d_in[5];
    const float* bv = (const float*)d_in[6];
    const float* wo = (const float*)d_in[7];
    const float* bo = (const float*)d_in[8];
    float* out = (float*)d_out;

    __half *xhi, *qhi, *khi, *vhi, *ahi, *whi;
    cudaGetSymbolAddress((void**)&xhi, g_xhi);
    cudaGetSymbolAddress((void**)&qhi, g_qhi);
    cudaGetSymbolAddress((void**)&khi, g_khi);
    cudaGetSymbolAddress((void**)&vhi, g_vhi);
    cudaGetSymbolAddress((void**)&ahi, g_ahi);
    cudaGetSymbolAddress((void**)&whi, g_whi);

    cudaFuncSetAttribute(gemm_mma<true>,  cudaFuncAttributeMaxDynamicSharedMemorySize, GEMM_SMEM);
    cudaFuncSetAttribute(gemm_mma<false>, cudaFuncAttributeMaxDynamicSharedMemorySize, GEMM_SMEM);
    cudaFuncSetAttribute(attn_mma, cudaFuncAttributeMaxDynamicSharedMemorySize, ATTN_SMEM);

    // 1) merged conversions: W transpose (z=0..3) + x fp16 convert (z=4..7)
    convert_kernel<<<dim3(32, 32, 8), dim3(32, 8)>>>(x, wq, wk, wv, wo, xhi, whi);

    // 2) QKV projections -> fp16 (Q pre-scaled by log2e/32)
    gemm_mma<true><<<dim3(8, 32, 3), 256, GEMM_SMEM>>>(
        xhi, whi, bq, bk, bv,
        nullptr,
        qhi, khi, vhi,
        QSCALE, 1.0f, 1.0f);

    // 3) Tensor-core windowed attention -> fp16
    attn_mma<<<dim3(SEQ / 64, HEADS, BATCH), 128, ATTN_SMEM>>>(
        qhi, khi, vhi, ahi);

    // 4) Output projection -> fp32
    gemm_mma<false><<<dim3(8, 32, 1), 256, GEMM_SMEM>>>(
        ahi, whi + (size_t)3 * EMB * EMB,
        bo, bo, bo,
        out,
        nullptr, nullptr, nullptr,
        1.0f, 1.0f, 1.0f);
}

// round 16
// speedup vs baseline: 1.0428x; 1.0283x over previous
#include <cuda_runtime.h>
#include <cuda_fp16.h>
#include <math.h>

#define EMB    1024
#define HEADS  16
#define DHEAD  64
#define WINDOW 128
#define BATCH  2
#define SEQ    2048
#define MTOT   (BATCH * SEQ)

// log2(e)/32 : folded into Q so softmax uses exp2
#define QSCALE 0.04508422f

// ---------------------------------------------------------------------------
// Device-global scratch
// ---------------------------------------------------------------------------
__device__ __half g_xhi[MTOT * EMB];
__device__ __half g_qhi[MTOT * EMB];
__device__ __half g_khi[MTOT * EMB];
__device__ __half g_vhi[MTOT * EMB];
__device__ __half g_ahi[MTOT * EMB];
__device__ __half g_whi[4 * EMB * EMB];   // transposed: [n][k], fp16

// ---------------------------------------------------------------------------
// PTX helpers
// ---------------------------------------------------------------------------
__device__ __forceinline__ unsigned s2u(const void* p) {
    unsigned a;
    asm("{ .reg .u64 t; cvta.to.shared.u64 t, %1; cvt.u32.u64 %0, t; }"
        : "=r"(a) : "l"(p));
    return a;
}
__device__ __forceinline__ void cp16(unsigned s, const void* g) {
    asm volatile("cp.async.cg.shared.global [%0], [%1], 16;" :: "r"(s), "l"(g));
}
#define CPA_COMMIT() asm volatile("cp.async.commit_group;" ::: "memory")
#define CPA_WAIT1()  asm volatile("cp.async.wait_group 1;" ::: "memory")
#define CPA_WAIT2()  asm volatile("cp.async.wait_group 2;" ::: "memory")

__device__ __forceinline__ void ldsm4(unsigned* r, unsigned a) {
    asm volatile("ldmatrix.sync.aligned.m8n8.x4.shared.b16 {%0,%1,%2,%3}, [%4];"
                 : "=r"(r[0]), "=r"(r[1]), "=r"(r[2]), "=r"(r[3]) : "r"(a));
}
__device__ __forceinline__ void ldsm4t(unsigned* r, unsigned a) {
    asm volatile("ldmatrix.sync.aligned.m8n8.x4.trans.shared.b16 {%0,%1,%2,%3}, [%4];"
                 : "=r"(r[0]), "=r"(r[1]), "=r"(r[2]), "=r"(r[3]) : "r"(a));
}
__device__ __forceinline__ void mma16816(float* c, const unsigned* a, const unsigned* b) {
    asm volatile(
        "mma.sync.aligned.m16n8k16.row.col.f32.f16.f16.f32 "
        "{%0,%1,%2,%3}, {%4,%5,%6,%7}, {%8,%9}, {%0,%1,%2,%3};"
        : "+f"(c[0]), "+f"(c[1]), "+f"(c[2]), "+f"(c[3])
        : "r"(a[0]), "r"(a[1]), "r"(a[2]), "r"(a[3]), "r"(b[0]), "r"(b[1]));
}

// guaranteed-MUFU exp2
__device__ __forceinline__ float ex2(float x) {
    float y;
    asm("ex2.approx.ftz.f32 %0, %1;" : "=f"(y) : "f"(x));
    return y;
}

// swizzled smem byte offset for (row, 16B-segment): rows of 128 bytes
__device__ __forceinline__ unsigned swz(int row, int seg) {
    return (unsigned)(row * 128 + ((seg ^ (row & 7)) << 4));
}

__device__ __forceinline__ unsigned pack2h(float a, float b) {
    __half2 h = __floats2half2_rn(a, b);
    return *reinterpret_cast<unsigned*>(&h);
}

// ---------------------------------------------------------------------------
// Merged conversion kernel: z=0..3 -> transpose+convert W_z; z=4..7 -> x->fp16
// grid (32, 32, 8), block (32, 8) = 256 threads
// ---------------------------------------------------------------------------
__global__ void convert_kernel(
    const float* __restrict__ x,
    const float* __restrict__ w0, const float* __restrict__ w1,
    const float* __restrict__ w2, const float* __restrict__ w3,
    __half* __restrict__ xhi, __half* __restrict__ whi)
{
    int z = blockIdx.z;
    if (z < 4) {
        __shared__ float t[32][33];
        const float* W = (z == 0) ? w0 : (z == 1) ? w1 : (z == 2) ? w2 : w3;
        int n0 = blockIdx.x * 32, k0 = blockIdx.y * 32;
        #pragma unroll
        for (int i = 0; i < 4; i++) {
            int k = threadIdx.y + i * 8;
            t[k][threadIdx.x] = W[(size_t)(k0 + k) * EMB + n0 + threadIdx.x];
        }
        __syncthreads();
        size_t base = (size_t)z * EMB * EMB;
        #pragma unroll
        for (int i = 0; i < 4; i++) {
            int n = threadIdx.y + i * 8;
            whi[base + (size_t)(n0 + n) * EMB + k0 + threadIdx.x] =
                __float2half_rn(t[threadIdx.x][n]);
        }
    } else {
        int bid = ((z - 4) * 1024) + blockIdx.y * 32 + blockIdx.x;
        int tid = threadIdx.y * 32 + threadIdx.x;
        int i = bid * 256 + tid;
        float4 v = reinterpret_cast<const float4*>(x)[i];
        reinterpret_cast<unsigned*>(xhi)[2 * i + 0] = pack2h(v.x, v.y);
        reinterpret_cast<unsigned*>(xhi)[2 * i + 1] = pack2h(v.z, v.w);
    }
}

// ---------------------------------------------------------------------------
// 1-pass fp16 mma.sync GEMM: C = Ah @ Wh + bias
// 128x128 CTA tile, BK=64, 3-stage cp.async pipeline.
// 4 warps (2m x 2n), warp tile 64x64 -> smem reads per chunk cut 96->64 KB.
// 128 threads/CTA, 2 CTAs/SM (256 regs/thread available, no spill).
// HALFOUT=true: fp16 out with per-z scale.  false: fp32 out.
// ---------------------------------------------------------------------------
#define BKC        64
#define TILE_HB    16384              // 128 rows x 128 B
#define STAGE_HB   (2 * TILE_HB)      // Ah, Bh
#define GSTAGES    3
#define NCHUNK     (EMB / BKC)        // 16
#define GEMM_SMEM  (GSTAGES * STAGE_HB)   // 98304

__device__ __forceinline__ void load_stage(
    unsigned st, int tid, int m0, int n0, int k0,
    const __half* Ah, const __half* Bh)
{
    #pragma unroll
    for (int i = 0; i < 8; i++) {
        int idx = tid + i * 128;
        int r   = idx >> 3;
        int s   = idx & 7;
        unsigned sw = swz(r, s);
        cp16(st + sw,           Ah + (size_t)(m0 + r) * EMB + k0 + s * 8);
        cp16(st + TILE_HB + sw, Bh + (size_t)(n0 + r) * EMB + k0 + s * 8);
    }
}

template<bool HALFOUT>
__global__ __launch_bounds__(128, 2) void gemm_mma(
    const __half* __restrict__ Ahi,
    const __half* __restrict__ Whi,
    const float* __restrict__ b0, const float* __restrict__ b1, const float* __restrict__ b2,
    float* __restrict__ Cf0,
    __half* __restrict__ Ch0, __half* __restrict__ Ch1, __half* __restrict__ Ch2,
    float s0, float s1, float s2)
{
    extern __shared__ char smc[];
    const int z = blockIdx.z;
    const float* bias = (z == 0) ? b0 : (z == 1) ? b1 : b2;
    __half* Ch = (z == 0) ? Ch0 : (z == 1) ? Ch1 : Ch2;
    float scale = (z == 0) ? s0 : (z == 1) ? s1 : s2;
    const __half* Bh = Whi + (size_t)z * EMB * EMB;
    const int m0  = blockIdx.y * 128;
    const int n0  = blockIdx.x * 128;
    const int tid = threadIdx.x;
    const int wid = tid >> 5, lane = tid & 31;
    const int wm  = wid & 1;          // 0..1 : 64 rows
    const int wn  = wid >> 1;         // 0..1 : 64 cols
    const unsigned sb = s2u(smc);

    float acc[4][8][4];
    #pragma unroll
    for (int mt = 0; mt < 4; mt++)
        #pragma unroll
        for (int nt = 0; nt < 8; nt++)
            #pragma unroll
            for (int e = 0; e < 4; e++) acc[mt][nt][e] = 0.0f;

    load_stage(sb,                tid, m0, n0, 0,       Ahi, Bh);
    CPA_COMMIT();
    load_stage(sb + STAGE_HB,     tid, m0, n0, BKC,     Ahi, Bh);
    CPA_COMMIT();
    load_stage(sb + 2 * STAGE_HB, tid, m0, n0, 2 * BKC, Ahi, Bh);
    CPA_COMMIT();

    const int arow  = wm * 64 + (lane & 15);                      // + mt*16
    const int aseg  = lane >> 4;
    const int brow4 = wn * 64 + ((lane >> 4) << 3) + (lane & 7);  // + nth*16
    const int bseg  = (lane >> 3) & 1;

    for (int c = 0; c < NCHUNK; c++) {
        unsigned st = sb + (unsigned)(c % GSTAGES) * STAGE_HB;
        CPA_WAIT2();
        __syncthreads();

        #pragma unroll
        for (int k8 = 0; k8 < 8; k8 += 2) {
            unsigned bh[8][2];
            #pragma unroll
            for (int nth = 0; nth < 4; nth++) {
                unsigned off = swz(brow4 + nth * 16, k8 + bseg);
                unsigned t4[4];
                ldsm4(t4, st + TILE_HB + off);
                bh[2 * nth][0] = t4[0]; bh[2 * nth][1] = t4[1];
                bh[2 * nth + 1][0] = t4[2]; bh[2 * nth + 1][1] = t4[3];
            }
            #pragma unroll
            for (int mt = 0; mt < 4; mt++) {
                unsigned off = swz(arow + mt * 16, k8 + aseg);
                unsigned ah[4];
                ldsm4(ah, st + off);
                #pragma unroll
                for (int nt = 0; nt < 8; nt++)
                    mma16816(acc[mt][nt], ah, bh[nt]);
            }
        }
        __syncthreads();
        int cn = c + 3;
        if (cn < NCHUNK) {
            load_stage(st, tid, m0, n0, cn * BKC, Ahi, Bh);
            CPA_COMMIT();
        }
    }

    #pragma unroll
    for (int mt = 0; mt < 4; mt++) {
        int rbase = m0 + wm * 64 + mt * 16 + (lane >> 2);
        #pragma unroll
        for (int nt = 0; nt < 8; nt++) {
            int col = n0 + wn * 64 + nt * 8 + 2 * (lane & 3);
            float2 bv = *reinterpret_cast<const float2*>(&bias[col]);
            float v0 = acc[mt][nt][0] + bv.x;
            float v1 = acc[mt][nt][1] + bv.y;
            float v2 = acc[mt][nt][2] + bv.x;
            float v3 = acc[mt][nt][3] + bv.y;
            if (HALFOUT) {
                *reinterpret_cast<unsigned*>(&Ch[(size_t)rbase * EMB + col]) =
                    pack2h(v0 * scale, v1 * scale);
                *reinterpret_cast<unsigned*>(&Ch[(size_t)(rbase + 8) * EMB + col]) =
                    pack2h(v2 * scale, v3 * scale);
            } else {
                float2 o0 = {v0, v1}, o1 = {v2, v3};
                *reinterpret_cast<float2*>(&Cf0[(size_t)rbase * EMB + col]) = o0;
                *reinterpret_cast<float2*>(&Cf0[(size_t)(rbase + 8) * EMB + col]) = o1;
            }
        }
    }
}

// ---------------------------------------------------------------------------
// Tensor-core windowed attention, fp16 K/V, MUFU softmax. (R13 best config)
// Q tile 64, 128 threads, 3-stage cp.async pipeline, one sync per tile.
// ---------------------------------------------------------------------------
#define KV_TILE   8192                 // 64 rows x 128 B
#define KV_STAGE  (2 * KV_TILE)        // Kh, Vh
#define ASTAGES   3
#define ATTN_SMEM (KV_TILE + ASTAGES * KV_STAGE)   // 57344

__device__ __forceinline__ void load_kv(
    unsigned st, int tid, int b, int kt, int h,
    const __half* Kh, const __half* Vh)
{
    #pragma unroll
    for (int i = 0; i < 4; i++) {
        int idx = tid + i * 128;
        int r = idx >> 3, s = idx & 7;
        unsigned sw = swz(r, s);
        size_t g = (size_t)(b * SEQ + kt + r) * EMB + h * DHEAD + s * 8;
        cp16(st + sw,           Kh + g);
        cp16(st + KV_TILE + sw, Vh + g);
    }
}

__global__ __launch_bounds__(128) void attn_mma(
    const __half* __restrict__ Qh,
    const __half* __restrict__ Kh,
    const __half* __restrict__ Vh,
    __half* __restrict__ Ohi)
{
    extern __shared__ char smb[];
    const unsigned sb = s2u(smb);
    const unsigned Qhi_s = sb;
    const unsigned st0   = sb + KV_TILE;

    const int tid = threadIdx.x, wid = tid >> 5, lane = tid & 31;
    const int q0 = blockIdx.x * 64, h = blockIdx.y, b = blockIdx.z;

    int kstart = q0 - 128; if (kstart < 0) kstart = 0;
    int kend   = q0 + 192; if (kend > SEQ) kend = SEQ;
    const int ntiles = (kend - kstart) >> 6;   // 3..5

    {
        const size_t qg = (size_t)(b * SEQ + q0) * EMB + h * DHEAD;
        #pragma unroll
        for (int i = 0; i < 4; i++) {
            int idx = tid + i * 128;
            int r = idx >> 3, s = idx & 7;
            cp16(Qhi_s + swz(r, s), Qh + qg + (size_t)r * EMB + s * 8);
        }
    }
    CPA_COMMIT();
    load_kv(st0,            tid, b, kstart,      h, Kh, Vh);
    CPA_COMMIT();
    load_kv(st0 + KV_STAGE, tid, b, kstart + 64, h, Kh, Vh);
    CPA_COMMIT();

    CPA_WAIT2();
    __syncthreads();

    unsigned qfh[4][4];
    {
        int qrow = wid * 16 + (lane & 15);
        int aks  = lane >> 4;
        #pragma unroll
        for (int kc = 0; kc < 4; kc++)
            ldsm4(qfh[kc], Qhi_s + swz(qrow, kc * 2 + aks));
    }

    float o[8][4];
    #pragma unroll
    for (int i = 0; i < 8; i++)
        #pragma unroll
        for (int e = 0; e < 4; e++) o[i][e] = 0.0f;
    float m0 = -1e30f, m1 = -1e30f, l0 = 0.0f, l1 = 0.0f;

    for (int t = 0; t < ntiles; t++) {
        CPA_WAIT1();
        __syncthreads();

        int tn = t + 2;
        if (tn < ntiles) {
            load_kv(st0 + (unsigned)(tn % ASTAGES) * KV_STAGE,
                    tid, b, kstart + tn * 64, h, Kh, Vh);
            CPA_COMMIT();
        }

        unsigned st = st0 + (unsigned)(t % ASTAGES) * KV_STAGE;
        const int kt = kstart + t * 64;

        // ---- S = Q K^T ----
        float s[8][4];
        #pragma unroll
        for (int i = 0; i < 8; i++)
            #pragma unroll
            for (int e = 0; e < 4; e++) s[i][e] = 0.0f;

        #pragma unroll
        for (int np = 0; np < 4; np++) {
            int krow = np * 16 + ((lane >> 4) << 3) + (lane & 7);
            #pragma unroll
            for (int kc = 0; kc < 4; kc++) {
                unsigned off = swz(krow, kc * 2 + ((lane >> 3) & 1));
                unsigned kb[4];
                ldsm4(kb, st + off);
                mma16816(s[2 * np],     qfh[kc], kb);
                mma16816(s[2 * np + 1], qfh[kc], kb + 2);
            }
        }

        // ---- window mask (only edge tiles) ----
        if (kt == q0 + 128 || kt + 128 == q0) {
            int iqb = q0 + wid * 16 + (lane >> 2);
            int jkb = kt + 2 * (lane & 3);
            #pragma unroll
            for (int nt = 0; nt < 8; nt++)
                #pragma unroll
                for (int e = 0; e < 4; e++) {
                    int iq = iqb + ((e >> 1) << 3);
                    int jk = jkb + nt * 8 + (e & 1);
                    int d = iq - jk; if (d < 0) d = -d;
                    if (d > WINDOW) s[nt][e] = -1e30f;
                }
        }

        // ---- online softmax (MUFU exp2) ----
        float mx0 = -1e30f, mx1 = -1e30f;
        #pragma unroll
        for (int nt = 0; nt < 8; nt++) {
            mx0 = fmaxf(mx0, fmaxf(s[nt][0], s[nt][1]));
            mx1 = fmaxf(mx1, fmaxf(s[nt][2], s[nt][3]));
        }
        mx0 = fmaxf(mx0, __shfl_xor_sync(0xffffffffu, mx0, 1));
        mx0 = fmaxf(mx0, __shfl_xor_sync(0xffffffffu, mx0, 2));
        mx1 = fmaxf(mx1, __shfl_xor_sync(0xffffffffu, mx1, 1));
        mx1 = fmaxf(mx1, __shfl_xor_sync(0xffffffffu, mx1, 2));
        float nm0 = fmaxf(m0, mx0), nm1 = fmaxf(m1, mx1);
        float c0 = ex2(m0 - nm0), c1 = ex2(m1 - nm1);
        m0 = nm0; m1 = nm1;
        l0 *= c0;  l1 *= c1;
        #pragma unroll
        for (int nt = 0; nt < 8; nt++) {
            o[nt][0] *= c0; o[nt][1] *= c0;
            o[nt][2] *= c1; o[nt][3] *= c1;
        }

        unsigned pha[4][4];
        #pragma unroll
        for (int np = 0; np < 4; np++) {
            float pe0 = ex2(s[2 * np][0] - m0), pe1 = ex2(s[2 * np][1] - m0);
            float pe2 = ex2(s[2 * np][2] - m1), pe3 = ex2(s[2 * np][3] - m1);
            float po0 = ex2(s[2 * np + 1][0] - m0), po1 = ex2(s[2 * np + 1][1] - m0);
            float po2 = ex2(s[2 * np + 1][2] - m1), po3 = ex2(s[2 * np + 1][3] - m1);
            l0 += pe0 + pe1 + po0 + po1;
            l1 += pe2 + pe3 + po2 + po3;
            pha[np][0] = pack2h(pe0, pe1);
            pha[np][1] = pack2h(pe2, pe3);
            pha[np][2] = pack2h(po0, po1);
            pha[np][3] = pack2h(po2, po3);
        }

        // ---- O += P V ----
        #pragma unroll
        for (int kc2 = 0; kc2 < 4; kc2++) {
            int vrow = kc2 * 16 + (lane & 15);
            #pragma unroll
            for (int dp = 0; dp < 4; dp++) {
                unsigned off = swz(vrow, dp * 2 + (lane >> 4));
                unsigned vb[4];
                ldsm4t(vb, st + KV_TILE + off);
                mma16816(o[2 * dp],     pha[kc2], vb);
                mma16816(o[2 * dp + 1], pha[kc2], vb + 2);
            }
        }
    }

    l0 += __shfl_xor_sync(0xffffffffu, l0, 1);
    l0 += __shfl_xor_sync(0xffffffffu, l0, 2);
    l1 += __shfl_xor_sync(0xffffffffu, l1, 1);
    l1 += __shfl_xor_sync(0xffffffffu, l1, 2);
    float inv0 = 1.0f / l0, inv1 = 1.0f / l1;

    int row0 = q0 + wid * 16 + (lane >> 2);
    size_t t0 = (size_t)(b * SEQ + row0) * EMB + h * DHEAD;
    size_t t1 = t0 + (size_t)8 * EMB;
    #pragma unroll
    for (int nt = 0; nt < 8; nt++) {
        int col = nt * 8 + 2 * (lane & 3);
        *reinterpret_cast<unsigned*>(&Ohi[t0 + col]) = pack2h(o[nt][0] * inv0, o[nt][1] * inv0);
        *reinterpret_cast<unsigned*>(&Ohi[t1 + col]) = pack2h(o[nt][2] * inv1, o[nt][3] * inv1);
    }
}

// ---------------------------------------------------------------------------
// Launch
// ---------------------------------------------------------------------------
extern "C" void kernel_launch(void* const* d_in, const int* in_sizes, int n_in,
                              void* d_out, int out_size)
{
    const float* x  = (const float*)d_in[0];
    const float* wq = (const float*)d_in[1];
    const float* bq = (const float*)d_in[2];
    const float* wk = (const float*)d_in[3];
    const float* bk = (const float*)d_in[4];
    const float* wv = (const float*)d_in[5];
    const float* bv = (const float*)d_in[6];
    const float* wo = (const float*)d_in[7];
    const float* bo = (const float*)d_in[8];
    float* out = (float*)d_out;

    __half *xhi, *qhi, *khi, *vhi, *ahi, *whi;
    cudaGetSymbolAddress((void**)&xhi, g_xhi);
    cudaGetSymbolAddress((void**)&qhi, g_qhi);
    cudaGetSymbolAddress((void**)&khi, g_khi);
    cudaGetSymbolAddress((void**)&vhi, g_vhi);
    cudaGetSymbolAddress((void**)&ahi, g_ahi);
    cudaGetSymbolAddress((void**)&whi, g_whi);

    cudaFuncSetAttribute(gemm_mma<true>,  cudaFuncAttributeMaxDynamicSharedMemorySize, GEMM_SMEM);
    cudaFuncSetAttribute(gemm_mma<false>, cudaFuncAttributeMaxDynamicSharedMemorySize, GEMM_SMEM);
    cudaFuncSetAttribute(attn_mma, cudaFuncAttributeMaxDynamicSharedMemorySize, ATTN_SMEM);

    // 1) merged conversions: W transpose (z=0..3) + x fp16 convert (z=4..7)
    convert_kernel<<<dim3(32, 32, 8), dim3(32, 8)>>>(x, wq, wk, wv, wo, xhi, whi);

    // 2) QKV projections -> fp16 (Q pre-scaled by log2e/32)
    gemm_mma<true><<<dim3(8, 32, 3), 128, GEMM_SMEM>>>(
        xhi, whi, bq, bk, bv,
        nullptr,
        qhi, khi, vhi,
        QSCALE, 1.0f, 1.0f);

    // 3) Tensor-core windowed attention -> fp16
    attn_mma<<<dim3(SEQ / 64, HEADS, BATCH), 128, ATTN_SMEM>>>(
        qhi, khi, vhi, ahi);

    // 4) Output projection -> fp32
    gemm_mma<false><<<dim3(8, 32, 1), 128, GEMM_SMEM>>>(
        ahi, whi + (size_t)3 * EMB * EMB,
        bo, bo, bo,
        out,
        nullptr, nullptr, nullptr,
        1.0f, 1.0f, 1.0f);
}